// round 10
// baseline (speedup 1.0000x reference)
#include <cuda_runtime.h>
#include <cuda_bf16.h>

#define NROWS    8192
#define NF       1024
#define NTHREADS 256
#define NB1      1024            // phase-1 blocks (8 warps = 8 rows each)
#define NB2      888             // phase-2 blocks = 148 SMs * 6 CTAs -> 1 wave
#define MAXK     10              // ceil(8192/888)

__device__ float2 g_stats[NROWS];    // {mu, rstd} per row

// ---------------- Phase 1: one warp per row -> row stats ----------------
__global__ __launch_bounds__(NTHREADS)
void kan_stats(const float* __restrict__ x)
{
    const int wid  = threadIdx.x >> 5;
    const int lane = threadIdx.x & 31;
    const int row  = blockIdx.x * 8 + wid;

    const float4* xr = reinterpret_cast<const float4*>(x + (size_t)row * NF);

    float sum = 0.0f, sq = 0.0f;
    #pragma unroll
    for (int k = 0; k < 8; k++) {
        const float4 t = xr[k * 32 + lane];
        sum += (t.x + t.y) + (t.z + t.w);
        sq   = fmaf(t.x, t.x, fmaf(t.y, t.y, fmaf(t.z, t.z, fmaf(t.w, t.w, sq))));
    }

    #pragma unroll
    for (int off = 16; off; off >>= 1) {
        sum += __shfl_xor_sync(0xffffffffu, sum, off);
        sq  += __shfl_xor_sync(0xffffffffu, sq,  off);
    }

    if (lane == 0) {
        const float mu = sum * (1.0f / NF);
        g_stats[row] = make_float2(mu,
            rsqrtf(sq * (1.0f / NF) - mu * mu + 1e-5f));
    }
}

// ---------------- Phase 2: pure elementwise map (no sync) ----------------
__global__ __launch_bounds__(NTHREADS)
void kan_map(const float* __restrict__ x,
             const float* __restrict__ lnw,
             const float* __restrict__ lnb,
             const float* __restrict__ sw,
             const float* __restrict__ bw,
             const float* __restrict__ grid,
             float* __restrict__ out)
{
    // Swizzled transposed planes: coeff i of feature f at i*1024 + (f&3)*256 + (f>>2).
    // Thread tid owns features 4*tid+c -> tap addr = i*1024 + c*256 + tid,
    // bank = tid mod 32 = lane: conflict-free under divergent plane index.
    __shared__ float s_swT[8 * NF];

    const int tid = threadIdx.x;

    for (int f = tid; f < NF; f += NTHREADS) {
        float4 a = *reinterpret_cast<const float4*>(sw + f * 8);
        float4 b = *reinterpret_cast<const float4*>(sw + f * 8 + 4);
        const int base = ((f & 3) << 8) + (f >> 2);
        s_swT[0 * NF + base] = a.x * (1.0f/6.0f);
        s_swT[1 * NF + base] = a.y * (1.0f/6.0f);
        s_swT[2 * NF + base] = a.z * (1.0f/6.0f);
        s_swT[3 * NF + base] = a.w * (1.0f/6.0f);
        s_swT[4 * NF + base] = b.x * (1.0f/6.0f);
        s_swT[5 * NF + base] = b.y * (1.0f/6.0f);
        s_swT[6 * NF + base] = b.z * (1.0f/6.0f);
        s_swT[7 * NF + base] = b.w * (1.0f/6.0f);
    }

    const float g0    = grid[0];
    const float g11   = grid[11];
    const float inv_h = 11.0f / (g11 - g0);
    const float h     = (g11 - g0) * (1.0f / 11.0f);

    const float4 w4 = *reinterpret_cast<const float4*>(lnw + 4 * tid);
    const float4 b4 = *reinterpret_cast<const float4*>(lnb + 4 * tid);
    const float4 s4 = *reinterpret_cast<const float4*>(bw  + 4 * tid);
    float A[4], G[4], W[4];
    A[0] = w4.x * inv_h; A[1] = w4.y * inv_h; A[2] = w4.z * inv_h; A[3] = w4.w * inv_h;
    G[0] = (b4.x - g0) * inv_h; G[1] = (b4.y - g0) * inv_h;
    G[2] = (b4.z - g0) * inv_h; G[3] = (b4.w - g0) * inv_h;
    W[0] = s4.x; W[1] = s4.y; W[2] = s4.z; W[3] = s4.w;

    // Tap base pointers per c, pre-shifted by -3 planes (i0 = j-3 folded in)
    const float* tapb[4];
    #pragma unroll
    for (int c = 0; c < 4; c++)
        tapb[c] = s_swT + (c << 8) + tid - 3 * NF;

    __syncthreads();   // only barrier: after table staging

    const size_t col = 4 * tid;

    #pragma unroll
    for (int k = 0; k < MAXK; k++) {
        const int row = blockIdx.x + k * NB2;
        if (row >= NROWS) break;    // blocks <200 do 10 rows, rest do 9

        const float4 v4 = *reinterpret_cast<const float4*>(
                              x + (size_t)row * NF + col);
        const float2 st = g_stats[row];
        const float v[4] = {v4.x, v4.y, v4.z, v4.w};
        const float mu   = st.x;
        const float rstd = st.y;

        float4 res;
        float* resp = &res.x;

        #pragma unroll
        for (int c = 0; c < 4; c++) {
            const float xn = fmaf((v[c] - mu) * rstd, A[c], G[c]); // knot units
            const float n  = fmaf(xn, h, g0);                      // normed

            const float fj = floorf(xn);
            const int   j  = (int)fj;
            const float t  = xn - fj;
            const float u  = 1.0f - t;
            const float t2 = t * t;
            const float u2 = u * u;
            const float B0 = u2 * u;
            const float B3 = t2 * t;
            const float B1 = fmaf(fmaf(3.0f, t, -6.0f), t2, 4.0f);
            const float B2 = fmaf(fmaf(3.0f, u, -6.0f), u2, 4.0f);

            // One base address + immediate-offset LDS taps
            const float* p = tapb[c] + (j << 10);
            const int i0 = j - 3;
            float s = 0.0f;
            if ((unsigned)(i0    ) < 8u) s = fmaf(B0, p[0 * NF], s);
            if ((unsigned)(i0 + 1) < 8u) s = fmaf(B1, p[1 * NF], s);
            if ((unsigned)(i0 + 2) < 8u) s = fmaf(B2, p[2 * NF], s);
            if ((unsigned)(i0 + 3) < 8u) s = fmaf(B3, p[3 * NF], s);

            // silu(n) = m + m*tanh(m), m = n/2  (MUFU tanh)
            const float m = 0.5f * n;
            float th;
            asm("tanh.approx.f32 %0, %1;" : "=f"(th) : "f"(m));
            const float sil = fmaf(m, th, m);

            resp[c] = fmaf(W[c], sil, s);
        }

        *reinterpret_cast<float4*>(out + (size_t)row * NF + col) = res;
    }
}

extern "C" void kernel_launch(void* const* d_in, const int* in_sizes, int n_in,
                              void* d_out, int out_size)
{
    const float* x    = (const float*)d_in[0];
    const float* lnw  = (const float*)d_in[1];
    const float* lnb  = (const float*)d_in[2];
    const float* sw   = (const float*)d_in[3];
    const float* bw   = (const float*)d_in[4];
    const float* grid = (const float*)d_in[5];
    float* out = (float*)d_out;

    kan_stats<<<NB1, NTHREADS>>>(x);
    kan_map<<<NB2, NTHREADS>>>(x, lnw, lnb, sw, bw, grid, out);
}

// round 11
// speedup vs baseline: 1.0721x; 1.0721x over previous
#include <cuda_runtime.h>
#include <cuda_bf16.h>

#define NROWS    8192
#define NF       1024
#define NTHREADS 256
#define NBLOCKS  1024
#define RPB      (NROWS / NBLOCKS)   // 8 rows per block in phase 2

__device__ float2 g_stats[NROWS];    // {mu, rstd} per row

// ---------------- Phase 1: one warp per row -> row stats ----------------
__global__ __launch_bounds__(NTHREADS)
void kan_stats(const float* __restrict__ x)
{
    const int wid  = threadIdx.x >> 5;
    const int lane = threadIdx.x & 31;
    const int row  = blockIdx.x * 8 + wid;

    const float4* xr = reinterpret_cast<const float4*>(x + (size_t)row * NF);

    float sum = 0.0f, sq = 0.0f;
    #pragma unroll
    for (int k = 0; k < 8; k++) {
        const float4 t = xr[k * 32 + lane];
        sum += (t.x + t.y) + (t.z + t.w);
        sq   = fmaf(t.x, t.x, fmaf(t.y, t.y, fmaf(t.z, t.z, fmaf(t.w, t.w, sq))));
    }

    #pragma unroll
    for (int off = 16; off; off >>= 1) {
        sum += __shfl_xor_sync(0xffffffffu, sum, off);
        sq  += __shfl_xor_sync(0xffffffffu, sq,  off);
    }

    if (lane == 0) {
        const float mu = sum * (1.0f / NF);
        g_stats[row] = make_float2(mu,
            rsqrtf(sq * (1.0f / NF) - mu * mu + 1e-5f));
    }
}

// ---------------- Phase 2: pure elementwise map (no sync) ----------------
__global__ __launch_bounds__(NTHREADS)
void kan_map(const float* __restrict__ x,
             const float* __restrict__ lnw,
             const float* __restrict__ lnb,
             const float* __restrict__ sw,
             const float* __restrict__ bw,
             const float* __restrict__ grid,
             float* __restrict__ out)
{
    // Swizzled transposed planes: coeff i of feature f at i*1024 + (f&3)*256 + (f>>2).
    // Thread tid owns features 4*tid+c -> tap addr = i*1024 + c*256 + tid,
    // bank = tid mod 32 = lane: conflict-free under divergent plane index.
    __shared__ float s_swT[8 * NF];

    const int tid = threadIdx.x;

    for (int f = tid; f < NF; f += NTHREADS) {
        float4 a = *reinterpret_cast<const float4*>(sw + f * 8);
        float4 b = *reinterpret_cast<const float4*>(sw + f * 8 + 4);
        const int base = ((f & 3) << 8) + (f >> 2);
        s_swT[0 * NF + base] = a.x * (1.0f/6.0f);
        s_swT[1 * NF + base] = a.y * (1.0f/6.0f);
        s_swT[2 * NF + base] = a.z * (1.0f/6.0f);
        s_swT[3 * NF + base] = a.w * (1.0f/6.0f);
        s_swT[4 * NF + base] = b.x * (1.0f/6.0f);
        s_swT[5 * NF + base] = b.y * (1.0f/6.0f);
        s_swT[6 * NF + base] = b.z * (1.0f/6.0f);
        s_swT[7 * NF + base] = b.w * (1.0f/6.0f);
    }

    const float g0    = grid[0];
    const float g11   = grid[11];
    const float inv_h = 11.0f / (g11 - g0);
    const float h     = (g11 - g0) * (1.0f / 11.0f);

    const float4 w4 = *reinterpret_cast<const float4*>(lnw + 4 * tid);
    const float4 b4 = *reinterpret_cast<const float4*>(lnb + 4 * tid);
    const float4 s4 = *reinterpret_cast<const float4*>(bw  + 4 * tid);
    float A[4], G[4], W[4];
    A[0] = w4.x * inv_h; A[1] = w4.y * inv_h; A[2] = w4.z * inv_h; A[3] = w4.w * inv_h;
    G[0] = (b4.x - g0) * inv_h; G[1] = (b4.y - g0) * inv_h;
    G[2] = (b4.z - g0) * inv_h; G[3] = (b4.w - g0) * inv_h;
    W[0] = s4.x; W[1] = s4.y; W[2] = s4.z; W[3] = s4.w;

    __syncthreads();   // only barrier: after table staging

    const size_t col = 4 * tid;
    float4 cur = *reinterpret_cast<const float4*>(
                     x + (size_t)blockIdx.x * NF + col);
    float2 st = g_stats[blockIdx.x];

    #pragma unroll
    for (int k = 0; k < RPB; k++) {
        const int row = blockIdx.x + k * NBLOCKS;

        // Prefetch next row's data + stats while this row computes
        float4 nxt;
        float2 stn;
        if (k + 1 < RPB) {
            nxt = *reinterpret_cast<const float4*>(
                      x + (size_t)(row + NBLOCKS) * NF + col);
            stn = g_stats[row + NBLOCKS];
        }

        const float v[4] = {cur.x, cur.y, cur.z, cur.w};
        const float mu   = st.x;
        const float rstd = st.y;

        float4 res;
        float* resp = &res.x;

        #pragma unroll
        for (int c = 0; c < 4; c++) {
            const float xn = fmaf((v[c] - mu) * rstd, A[c], G[c]); // knot units
            const float n  = fmaf(xn, h, g0);                      // normed

            const float fj = floorf(xn);
            const int   j  = (int)fj;
            const float t  = xn - fj;
            const float u  = 1.0f - t;
            const float t2 = t * t;
            const float u2 = u * u;
            const float B0 = u2 * u;
            const float B3 = t2 * t;
            const float B1 = fmaf(fmaf(3.0f, t, -6.0f), t2, 4.0f);
            const float B2 = fmaf(fmaf(3.0f, u, -6.0f), u2, 4.0f);

            // One base address + immediate-offset LDS taps (i0 = j-3 folded)
            const float* p = s_swT + (c << 8) + tid + ((j - 3) << 10);
            const int i0 = j - 3;
            float s = 0.0f;
            if ((unsigned)(i0    ) < 8u) s = fmaf(B0, p[0 * NF], s);
            if ((unsigned)(i0 + 1) < 8u) s = fmaf(B1, p[1 * NF], s);
            if ((unsigned)(i0 + 2) < 8u) s = fmaf(B2, p[2 * NF], s);
            if ((unsigned)(i0 + 3) < 8u) s = fmaf(B3, p[3 * NF], s);

            // silu(n) = m + m*tanh(m), m = n/2  (MUFU tanh)
            const float m = 0.5f * n;
            float th;
            asm("tanh.approx.f32 %0, %1;" : "=f"(th) : "f"(m));
            const float sil = fmaf(m, th, m);

            resp[c] = fmaf(W[c], sil, s);
        }

        *reinterpret_cast<float4*>(out + (size_t)row * NF + col) = res;
        cur = nxt;
        st  = stn;
    }
}

extern "C" void kernel_launch(void* const* d_in, const int* in_sizes, int n_in,
                              void* d_out, int out_size)
{
    const float* x    = (const float*)d_in[0];
    const float* lnw  = (const float*)d_in[1];
    const float* lnb  = (const float*)d_in[2];
    const float* sw   = (const float*)d_in[3];
    const float* bw   = (const float*)d_in[4];
    const float* grid = (const float*)d_in[5];
    float* out = (float*)d_out;

    kan_stats<<<NROWS / 8, NTHREADS>>>(x);
    kan_map<<<NBLOCKS, NTHREADS>>>(x, lnw, lnb, sw, bw, grid, out);
}

// round 12
// speedup vs baseline: 1.0816x; 1.0089x over previous
#include <cuda_runtime.h>
#include <cuda_bf16.h>

#define NROWS    8192
#define NF       1024
#define NTHREADS 256
#define NBLOCKS  1024
#define RPB      (NROWS / NBLOCKS)   // 8 rows per block in phase 2

__device__ float2 g_stats[NROWS];    // {mu, rstd} per row

// ---------------- Phase 1: one warp per row -> row stats ----------------
__global__ __launch_bounds__(NTHREADS)
void kan_stats(const float* __restrict__ x)
{
    const int wid  = threadIdx.x >> 5;
    const int lane = threadIdx.x & 31;
    const int row  = blockIdx.x * 8 + wid;

    const float4* xr = reinterpret_cast<const float4*>(x + (size_t)row * NF);

    float sum = 0.0f, sq = 0.0f;
    #pragma unroll
    for (int k = 0; k < 8; k++) {
        const float4 t = xr[k * 32 + lane];
        sum += (t.x + t.y) + (t.z + t.w);
        sq   = fmaf(t.x, t.x, fmaf(t.y, t.y, fmaf(t.z, t.z, fmaf(t.w, t.w, sq))));
    }

    #pragma unroll
    for (int off = 16; off; off >>= 1) {
        sum += __shfl_xor_sync(0xffffffffu, sum, off);
        sq  += __shfl_xor_sync(0xffffffffu, sq,  off);
    }

    if (lane == 0) {
        const float mu = sum * (1.0f / NF);
        g_stats[row] = make_float2(mu,
            rsqrtf(sq * (1.0f / NF) - mu * mu + 1e-5f));
    }
}

// ---------------- Phase 2: pure elementwise map (no sync) ----------------
// minBlocksPerMultiprocessor=6 forces regs <= 42 -> 6 CTAs/SM (smem fits: 33KB*6=198KB)
__global__ __launch_bounds__(NTHREADS, 6)
void kan_map(const float* __restrict__ x,
             const float* __restrict__ lnw,
             const float* __restrict__ lnb,
             const float* __restrict__ sw,
             const float* __restrict__ bw,
             const float* __restrict__ grid,
             float* __restrict__ out)
{
    // Swizzled transposed planes: coeff i of feature f at i*1024 + (f&3)*256 + (f>>2).
    // Thread tid owns features 4*tid+c -> tap addr = i*1024 + c*256 + tid,
    // bank = tid mod 32 = lane: conflict-free under divergent plane index.
    __shared__ float s_swT[8 * NF];

    const int tid = threadIdx.x;

    for (int f = tid; f < NF; f += NTHREADS) {
        float4 a = *reinterpret_cast<const float4*>(sw + f * 8);
        float4 b = *reinterpret_cast<const float4*>(sw + f * 8 + 4);
        const int base = ((f & 3) << 8) + (f >> 2);
        s_swT[0 * NF + base] = a.x * (1.0f/6.0f);
        s_swT[1 * NF + base] = a.y * (1.0f/6.0f);
        s_swT[2 * NF + base] = a.z * (1.0f/6.0f);
        s_swT[3 * NF + base] = a.w * (1.0f/6.0f);
        s_swT[4 * NF + base] = b.x * (1.0f/6.0f);
        s_swT[5 * NF + base] = b.y * (1.0f/6.0f);
        s_swT[6 * NF + base] = b.z * (1.0f/6.0f);
        s_swT[7 * NF + base] = b.w * (1.0f/6.0f);
    }

    const float g0    = grid[0];
    const float g11   = grid[11];
    const float inv_h = 11.0f / (g11 - g0);
    const float h     = (g11 - g0) * (1.0f / 11.0f);

    const float4 w4 = *reinterpret_cast<const float4*>(lnw + 4 * tid);
    const float4 b4 = *reinterpret_cast<const float4*>(lnb + 4 * tid);
    const float4 s4 = *reinterpret_cast<const float4*>(bw  + 4 * tid);
    float A[4], G[4], W[4];
    A[0] = w4.x * inv_h; A[1] = w4.y * inv_h; A[2] = w4.z * inv_h; A[3] = w4.w * inv_h;
    G[0] = (b4.x - g0) * inv_h; G[1] = (b4.y - g0) * inv_h;
    G[2] = (b4.z - g0) * inv_h; G[3] = (b4.w - g0) * inv_h;
    W[0] = s4.x; W[1] = s4.y; W[2] = s4.z; W[3] = s4.w;

    __syncthreads();   // only barrier: after table staging

    const size_t col = 4 * tid;
    float4 cur = *reinterpret_cast<const float4*>(
                     x + (size_t)blockIdx.x * NF + col);
    float2 st = g_stats[blockIdx.x];

    #pragma unroll
    for (int k = 0; k < RPB; k++) {
        const int row = blockIdx.x + k * NBLOCKS;

        // Prefetch next row's data + stats while this row computes
        float4 nxt;
        float2 stn;
        if (k + 1 < RPB) {
            nxt = *reinterpret_cast<const float4*>(
                      x + (size_t)(row + NBLOCKS) * NF + col);
            stn = g_stats[row + NBLOCKS];
        }

        const float v[4] = {cur.x, cur.y, cur.z, cur.w};
        const float mu   = st.x;
        const float rstd = st.y;

        float4 res;
        float* resp = &res.x;

        #pragma unroll
        for (int c = 0; c < 4; c++) {
            const float xn = fmaf((v[c] - mu) * rstd, A[c], G[c]); // knot units
            const float n  = fmaf(xn, h, g0);                      // normed

            const float fj = floorf(xn);
            const int   j  = (int)fj;
            const float t  = xn - fj;
            const float u  = 1.0f - t;
            const float t2 = t * t;
            const float u2 = u * u;
            const float B0 = u2 * u;
            const float B3 = t2 * t;
            const float B1 = fmaf(fmaf(3.0f, t, -6.0f), t2, 4.0f);
            const float B2 = fmaf(fmaf(3.0f, u, -6.0f), u2, 4.0f);

            // One base address + immediate-offset LDS taps (i0 = j-3 folded)
            const float* p = s_swT + (c << 8) + tid + ((j - 3) << 10);
            const int i0 = j - 3;
            float s = 0.0f;
            if ((unsigned)(i0    ) < 8u) s = fmaf(B0, p[0 * NF], s);
            if ((unsigned)(i0 + 1) < 8u) s = fmaf(B1, p[1 * NF], s);
            if ((unsigned)(i0 + 2) < 8u) s = fmaf(B2, p[2 * NF], s);
            if ((unsigned)(i0 + 3) < 8u) s = fmaf(B3, p[3 * NF], s);

            // silu(n) = m + m*tanh(m), m = n/2  (MUFU tanh)
            const float m = 0.5f * n;
            float th;
            asm("tanh.approx.f32 %0, %1;" : "=f"(th) : "f"(m));
            const float sil = fmaf(m, th, m);

            resp[c] = fmaf(W[c], sil, s);
        }

        *reinterpret_cast<float4*>(out + (size_t)row * NF + col) = res;
        cur = nxt;
        st  = stn;
    }
}

extern "C" void kernel_launch(void* const* d_in, const int* in_sizes, int n_in,
                              void* d_out, int out_size)
{
    const float* x    = (const float*)d_in[0];
    const float* lnw  = (const float*)d_in[1];
    const float* lnb  = (const float*)d_in[2];
    const float* sw   = (const float*)d_in[3];
    const float* bw   = (const float*)d_in[4];
    const float* grid = (const float*)d_in[5];
    float* out = (float*)d_out;

    kan_stats<<<NROWS / 8, NTHREADS>>>(x);
    kan_map<<<NBLOCKS, NTHREADS>>>(x, lnw, lnb, sw, bw, grid, out);
}